// round 9
// baseline (speedup 1.0000x reference)
#include <cuda_runtime.h>
#include <math.h>
#include <cstddef>
#include <stdint.h>

#define B_   4
#define L_   2048
#define D_   1024
#define H_   16
#define DKV  64

// ---------------------------------------------------------------------------
// Scratch (allocation-free: __device__ globals)
// ---------------------------------------------------------------------------
static __device__ float g_qh [(size_t)B_ * L_ * D_];      // (b,l,h*dk) natural
static __device__ float g_kh [(size_t)B_ * L_ * D_];      // (b,l,h*dk) d 8-perm
static __device__ float g_vt [(size_t)B_ * H_ * DKV * L_];// (bh,dv,l)  l 8-perm
static __device__ float g_ctx[(size_t)B_ * L_ * D_];
static __device__ float g_x  [(size_t)B_ * L_ * D_];
static __device__ float g_wt [4 * 1048576];               // Wt[n][k] tf32, k 8-perm
static __device__ unsigned long long g_mp[(size_t)B_ * L_ * 32];

// ---------------------------------------------------------------------------
// Helpers
// ---------------------------------------------------------------------------
__device__ __forceinline__ uint32_t f2tf(float f) {
    uint32_t u;
    asm("cvt.rna.tf32.f32 %0, %1;" : "=r"(u) : "f"(f));
    return u;
}
__device__ __forceinline__ float rndf(float x) { return __uint_as_float(f2tf(x)); }

// pair-interleave perm within 8-group: position 2c holds elem c, 2c+1 holds c+4
__device__ __forceinline__ int perm8(int n) {
    return (n & ~7) | (((n & 3) << 1) | ((n & 7) >> 2));
}

__device__ __forceinline__ void mma8(float4& d,
    uint32_t a0, uint32_t a1, uint32_t a2, uint32_t a3,
    uint32_t b0, uint32_t b1)
{
    asm volatile(
        "mma.sync.aligned.m16n8k8.row.col.f32.tf32.tf32.f32 "
        "{%0,%1,%2,%3}, {%4,%5,%6,%7}, {%8,%9}, {%0,%1,%2,%3};"
        : "+f"(d.x), "+f"(d.y), "+f"(d.z), "+f"(d.w)
        : "r"(a0), "r"(a1), "r"(a2), "r"(a3), "r"(b0), "r"(b1));
}

__device__ __forceinline__ void cp16(uint32_t dst, const void* src) {
    asm volatile("cp.async.ca.shared.global [%0], [%1], 16;" :: "r"(dst), "l"(src));
}
__device__ __forceinline__ void cpcommit() { asm volatile("cp.async.commit_group;"); }
__device__ __forceinline__ void cpwait0()  { asm volatile("cp.async.wait_group 0;"); }
__device__ __forceinline__ void cpwait1()  { asm volatile("cp.async.wait_group 1;"); }

// ---------------------------------------------------------------------------
// Weight transpose + tf32 round: Wt[n][perm8(k)] = rnd(W[k][n])
// ---------------------------------------------------------------------------
__global__ __launch_bounds__(256) void wt_kernel(
    const float* __restrict__ W, float* __restrict__ Wt)
{
    __shared__ float t[32][33];
    const int kt = blockIdx.x * 32, nt = blockIdx.y * 32;
    const int tx = threadIdx.x & 31, ty = threadIdx.x >> 5;
#pragma unroll
    for (int r = ty; r < 32; r += 8)
        t[r][tx] = W[(size_t)(kt + r) * D_ + nt + tx];
    __syncthreads();
#pragma unroll
    for (int r = ty; r < 32; r += 8) {
        int kp = perm8(tx);
        Wt[(size_t)(nt + r) * D_ + kt + kp] = rndf(t[tx][r]);
    }
}

// ---------------------------------------------------------------------------
// Mask bit-packing
// ---------------------------------------------------------------------------
__global__ __launch_bounds__(256) void pack_mask(
    const unsigned char* __restrict__ mask, unsigned long long* __restrict__ mp)
{
    int idx = blockIdx.x * blockDim.x + threadIdx.x;
    if (idx >= B_ * L_ * 32) return;
    const unsigned* s = (const unsigned*)(mask + (size_t)idx * 64);
    unsigned long long bits = 0;
#pragma unroll
    for (int i = 0; i < 16; i++) {
        unsigned v = __ldg(s + i);
        unsigned t = ((v & 0x000000FFu) ? 1u : 0u)
                   | ((v & 0x0000FF00u) ? 2u : 0u)
                   | ((v & 0x00FF0000u) ? 4u : 0u)
                   | ((v & 0xFF000000u) ? 8u : 0u);
        bits |= (unsigned long long)t << (i * 4);
    }
    mp[idx] = bits;
}

// ---------------------------------------------------------------------------
// GEMM body: acc = A[M,K] @ Wt^T + bias. Wt is [n][k] (k 8-perm, tf32).
// Epilogue modes: 0=qh(round,*0.125)  1=kh(round,col-perm)
//                 2=vt(round,transpose+l-perm)  3=out(+R raw)
// smem: As[2][128][40] + Wst[2][128][36]  (77824 B)
// ---------------------------------------------------------------------------
__device__ __forceinline__ void gemm_body(
    const float* __restrict__ A, const float* __restrict__ Wt,
    const float* __restrict__ bias, const float* __restrict__ R,
    float* __restrict__ C, int mode, char* smraw)
{
    float* As  = (float*)smraw;                  // 2*128*40
    float* Wst = (float*)smraw + 2 * 128 * 40;   // 2*128*36
    const int tid  = threadIdx.x;
    const int lane = tid & 31, wid = tid >> 5;
    const int wm = (wid & 3) * 32, wn = (wid >> 2) * 64;
    const int g = lane >> 2, c = lane & 3;
    const int bm = blockIdx.y * 128, bn = blockIdx.x * 128;
    const int K = D_, N = D_;

    uint32_t asBase = (uint32_t)__cvta_generic_to_shared(As);
    uint32_t wsBase = (uint32_t)__cvta_generic_to_shared(Wst);

    auto issue = [&](int buf, int kt) {
#pragma unroll
        for (int u = 0; u < 4; u++) {
            int i = tid + u * 256;
            int r = i >> 3, off = (i & 7) << 2;
            cp16(asBase + (uint32_t)(buf * 5120 + r * 40 + off) * 4,
                 A + (size_t)(bm + r) * K + kt + off);
        }
#pragma unroll
        for (int u = 0; u < 4; u++) {
            int i = tid + u * 256;
            int r = i >> 3, off = (i & 7) << 2;
            cp16(wsBase + (uint32_t)(buf * 4608 + r * 36 + off) * 4,
                 Wt + (size_t)(bn + r) * K + kt + off);
        }
        cpcommit();
    };

    float4 acc[2][8];
#pragma unroll
    for (int mi = 0; mi < 2; mi++)
#pragma unroll
        for (int j = 0; j < 8; j++) acc[mi][j] = make_float4(0.f, 0.f, 0.f, 0.f);

    issue(0, 0);
    int buf = 0;
    for (int kt = 0; kt < K; kt += 32) {
        if (kt + 32 < K) { issue(buf ^ 1, kt + 32); cpwait1(); }
        else             { cpwait0(); }
        __syncthreads();
        const float* Ab = As  + buf * 5120;
        const float* Wb = Wst + buf * 4608;
#pragma unroll
        for (int kk = 0; kk < 32; kk += 8) {
            uint32_t a[2][4];
#pragma unroll
            for (int mi = 0; mi < 2; mi++) {
                int r = wm + mi * 16;
                a[mi][0] = f2tf(Ab[(r + g    ) * 40 + kk + c]);
                a[mi][1] = f2tf(Ab[(r + g + 8) * 40 + kk + c]);
                a[mi][2] = f2tf(Ab[(r + g    ) * 40 + kk + c + 4]);
                a[mi][3] = f2tf(Ab[(r + g + 8) * 40 + kk + c + 4]);
            }
#pragma unroll
            for (int j = 0; j < 8; j++) {
                uint2 bb = *(const uint2*)&Wb[(wn + j * 8 + g) * 36 + kk + (c << 1)];
                mma8(acc[0][j], a[0][0], a[0][1], a[0][2], a[0][3], bb.x, bb.y);
                mma8(acc[1][j], a[1][0], a[1][1], a[1][2], a[1][3], bb.x, bb.y);
            }
        }
        __syncthreads();
        buf ^= 1;
    }

#pragma unroll
    for (int mi = 0; mi < 2; mi++) {
#pragma unroll
        for (int j = 0; j < 8; j++) {
            int r0  = bm + wm + mi * 16 + g;
            int col = bn + wn + j * 8 + (c << 1);
            float bx = bias[col], by = bias[col + 1];
            float2 v0 = { acc[mi][j].x + bx, acc[mi][j].y + by };
            float2 v1 = { acc[mi][j].z + bx, acc[mi][j].w + by };
            if (mode == 0) {
                v0.x = rndf(v0.x * 0.125f); v0.y = rndf(v0.y * 0.125f);
                v1.x = rndf(v1.x * 0.125f); v1.y = rndf(v1.y * 0.125f);
                *(float2*)(C + (size_t)r0 * N + col)       = v0;
                *(float2*)(C + (size_t)(r0 + 8) * N + col) = v1;
            } else if (mode == 1) {
                int c0 = perm8(col), c1 = perm8(col + 1);
                C[(size_t)r0 * N + c0]       = rndf(v0.x);
                C[(size_t)r0 * N + c1]       = rndf(v0.y);
                C[(size_t)(r0 + 8) * N + c0] = rndf(v1.x);
                C[(size_t)(r0 + 8) * N + c1] = rndf(v1.y);
            } else if (mode == 2) {
                // vt[(b*H+h)*64+dv][ perm8(l) ]
                int bb_ = r0 >> 11, l0 = r0 & 2047;
                int hh = col >> 6, dv = col & 63;
                size_t base  = ((size_t)(bb_ * H_ + hh) * DKV + dv) * L_;
                size_t base1 = base + L_;   // dv+1
                C[base  + perm8(l0)]     = rndf(v0.x);
                C[base1 + perm8(l0)]     = rndf(v0.y);
                C[base  + perm8(l0 + 8)] = rndf(v1.x);
                C[base1 + perm8(l0 + 8)] = rndf(v1.y);
            } else {
                float2 r0v = *(const float2*)(R + (size_t)r0 * N + col);
                float2 r1v = *(const float2*)(R + (size_t)(r0 + 8) * N + col);
                v0.x += r0v.x; v0.y += r0v.y;
                v1.x += r1v.x; v1.y += r1v.y;
                *(float2*)(C + (size_t)r0 * N + col)       = v0;
                *(float2*)(C + (size_t)(r0 + 8) * N + col) = v1;
            }
        }
    }
}

__global__ __launch_bounds__(256, 2) void qkv_gemm(
    const float* q, const float* k, const float* v,
    const float* Wtq, const float* Wtk, const float* Wtv,
    const float* bq, const float* bk, const float* bv,
    float* qh, float* kh, float* vt)
{
    extern __shared__ char sm[];
    int z = blockIdx.z;
    const float* A  = z == 0 ? q   : (z == 1 ? k   : v);
    const float* Wt = z == 0 ? Wtq : (z == 1 ? Wtk : Wtv);
    const float* b  = z == 0 ? bq  : (z == 1 ? bk  : bv);
    float*       C  = z == 0 ? qh  : (z == 1 ? kh  : vt);
    gemm_body(A, Wt, b, nullptr, C, z, sm);
}

__global__ __launch_bounds__(256, 2) void oproj_gemm(
    const float* ctx, const float* Wto, const float* bo,
    const float* R, float* C)
{
    extern __shared__ char sm[];
    gemm_body(ctx, Wto, bo, R, C, 3, sm);
}

// ---------------------------------------------------------------------------
// Fused attention: 128q block, K tiles of 64, two passes, no-max softmax.
// K/V cp.async double-buffered (LDS.64 fragments via gmem-side perms).
// smem (u32): Ks[2][64*68] Vs[2][64*68] Ps[128*68] = 104448 B
// ---------------------------------------------------------------------------
#define KT32 (64 * 68)

__global__ __launch_bounds__(256, 2) void attn_kernel(
    const float* __restrict__ qh, const float* __restrict__ kh,
    const float* __restrict__ vt, const unsigned long long* __restrict__ mp,
    float* __restrict__ attn, float* __restrict__ ctx, int write_attn)
{
    extern __shared__ uint32_t smu[];
    uint32_t* Ks = smu;                   // 2 bufs
    uint32_t* Vs = smu + 2 * KT32;        // 2 bufs
    uint32_t* Ps = smu + 4 * KT32;        // 128*68

    const int tid  = threadIdx.x;
    const int lane = tid & 31, wid = tid >> 5;
    const int g = lane >> 2, c = lane & 3;
    const int c2 = c << 1;
    const int q0 = blockIdx.x * 128;
    const int bh = blockIdx.y, b = bh >> 4;
    const int qw = wid * 16;

    const uint32_t smemB = (uint32_t)__cvta_generic_to_shared(smu);

    // Q fragments in registers (qh pre-scaled ×0.125, tf32, unpermuted)
    uint32_t aq[8][4];
    {
        const float* qb = qh + ((size_t)(b * L_ + q0 + qw)) * D_ + (bh & 15) * DKV;
#pragma unroll
        for (int s = 0; s < 8; s++) {
            aq[s][0] = __float_as_uint(__ldg(qb + (size_t)g       * D_ + s * 8 + c));
            aq[s][1] = __float_as_uint(__ldg(qb + (size_t)(g + 8) * D_ + s * 8 + c));
            aq[s][2] = __float_as_uint(__ldg(qb + (size_t)g       * D_ + s * 8 + c + 4));
            aq[s][3] = __float_as_uint(__ldg(qb + (size_t)(g + 8) * D_ + s * 8 + c + 4));
        }
    }

    auto issueK = [&](int bufi, int kt) {
        const float* kb = kh + ((size_t)(b * L_ + kt)) * D_ + (bh & 15) * DKV;
#pragma unroll
        for (int u = 0; u < 4; u++) {
            int i = tid + u * 256;
            int r = i >> 4, coff = (i & 15) << 2;
            cp16(smemB + (uint32_t)(bufi * KT32 + r * 68 + coff) * 4,
                 kb + (size_t)r * D_ + coff);
        }
    };
    auto issueV = [&](int bufi, int kt) {
        const float* vb = vt + (size_t)bh * DKV * L_ + kt;
#pragma unroll
        for (int u = 0; u < 4; u++) {
            int i = tid + u * 256;
            int r = i >> 4, coff = (i & 15) << 2;
            cp16(smemB + (uint32_t)((2 + bufi) * KT32 + r * 68 + coff) * 4,
                 vb + (size_t)r * L_ + coff);
        }
    };

    const int qg0 = q0 + qw + g;
    const int qg1 = qg0 + 8;
    const unsigned long long* mp0 = mp + (size_t)(b * L_ + qg0) * 32;
    const unsigned long long* mp1 = mp + (size_t)(b * L_ + qg1) * 32;

    float l0 = 0.f, l1 = 0.f;

    // ---------------- PASS 1: row sums of exp (no max needed) ----------------
    issueK(0, 0); cpcommit();
    int buf = 0;
    for (int kt = 0; kt < L_; kt += 64) {
        cpwait0();
        __syncthreads();
        if (kt + 64 < L_) { issueK(buf ^ 1, kt + 64); cpcommit(); }

        const uint32_t* Kb = Ks + buf * KT32;
        float4 S[8];
#pragma unroll
        for (int j = 0; j < 8; j++) S[j] = make_float4(0.f, 0.f, 0.f, 0.f);
#pragma unroll
        for (int s = 0; s < 8; s++) {
#pragma unroll
            for (int j = 0; j < 8; j++) {
                uint2 bb = *(const uint2*)&Kb[(j * 8 + g) * 68 + s * 8 + c2];
                mma8(S[j], aq[s][0], aq[s][1], aq[s][2], aq[s][3], bb.x, bb.y);
            }
        }

        unsigned long long w0 = mp0[kt >> 6], w1 = mp1[kt >> 6];
        if (w0 | w1) {
#pragma unroll
            for (int j = 0; j < 8; j++) {
                int bi = j * 8 + c2;
                if ((w0 >> bi)       & 1) S[j].x = -INFINITY;
                if ((w0 >> (bi + 1)) & 1) S[j].y = -INFINITY;
                if ((w1 >> bi)       & 1) S[j].z = -INFINITY;
                if ((w1 >> (bi + 1)) & 1) S[j].w = -INFINITY;
            }
        }
#pragma unroll
        for (int j = 0; j < 8; j++) {
            l0 += __expf(S[j].x) + __expf(S[j].y);
            l1 += __expf(S[j].z) + __expf(S[j].w);
        }
        buf ^= 1;
    }
    l0 += __shfl_xor_sync(0xffffffffu, l0, 1);
    l0 += __shfl_xor_sync(0xffffffffu, l0, 2);
    l1 += __shfl_xor_sync(0xffffffffu, l1, 1);
    l1 += __shfl_xor_sync(0xffffffffu, l1, 2);
    const float inv0 = 1.0f / l0;
    const float inv1 = 1.0f / l1;

    // ---------------- PASS 2: attn write + O = P@V ----------------
    float4 O[8];
#pragma unroll
    for (int j = 0; j < 8; j++) O[j] = make_float4(0.f, 0.f, 0.f, 0.f);

    // Ks[0] last read 2 tiles ago and all threads passed that barrier; safe.
    issueK(0, 0); issueV(0, 0); cpcommit();
    buf = 0;
    for (int kt = 0; kt < L_; kt += 64) {
        cpwait0();
        __syncthreads();
        if (kt + 64 < L_) { issueK(buf ^ 1, kt + 64); issueV(buf ^ 1, kt + 64); cpcommit(); }

        const uint32_t* Kb = Ks + buf * KT32;
        const uint32_t* Vb = Vs + buf * KT32;     // FIXED: Vs already offset
        float4 S[8];
#pragma unroll
        for (int j = 0; j < 8; j++) S[j] = make_float4(0.f, 0.f, 0.f, 0.f);
#pragma unroll
        for (int s = 0; s < 8; s++) {
#pragma unroll
            for (int j = 0; j < 8; j++) {
                uint2 bb = *(const uint2*)&Kb[(j * 8 + g) * 68 + s * 8 + c2];
                mma8(S[j], aq[s][0], aq[s][1], aq[s][2], aq[s][3], bb.x, bb.y);
            }
        }

        unsigned long long w0 = mp0[kt >> 6], w1 = mp1[kt >> 6];
        bool anymask = (w0 | w1) != 0ull;
#pragma unroll
        for (int j = 0; j < 8; j++) {
            float px = __expf(S[j].x) * inv0;
            float py = __expf(S[j].y) * inv0;
            float pz = __expf(S[j].z) * inv1;
            float pw = __expf(S[j].w) * inv1;
            if (anymask) {
                int bi = j * 8 + c2;
                if ((w0 >> bi)       & 1) px = 0.f;
                if ((w0 >> (bi + 1)) & 1) py = 0.f;
                if ((w1 >> bi)       & 1) pz = 0.f;
                if ((w1 >> (bi + 1)) & 1) pw = 0.f;
            }
            int kcol = kt + j * 8 + c2;
            if (write_attn) {
                *(float2*)(attn + ((size_t)bh * L_ + qg0) * L_ + kcol) = make_float2(px, py);
                *(float2*)(attn + ((size_t)bh * L_ + qg1) * L_ + kcol) = make_float2(pz, pw);
            }
            uint2 p01 = { f2tf(px), f2tf(py) };
            uint2 p23 = { f2tf(pz), f2tf(pw) };
            *(uint2*)&Ps[(qw + g    ) * 68 + j * 8 + c2] = p01;
            *(uint2*)&Ps[(qw + g + 8) * 68 + j * 8 + c2] = p23;
        }
        __syncwarp();   // Ps rows qw..qw+15 are warp-private

        // O += P @ V  (V rows = dv, cols = token with pair-perm)
#pragma unroll
        for (int s = 0; s < 8; s++) {
            uint32_t a0 = Ps[(qw + g    ) * 68 + s * 8 + c];
            uint32_t a1 = Ps[(qw + g + 8) * 68 + s * 8 + c];
            uint32_t a2 = Ps[(qw + g    ) * 68 + s * 8 + c + 4];
            uint32_t a3 = Ps[(qw + g + 8) * 68 + s * 8 + c + 4];
#pragma unroll
            for (int j = 0; j < 8; j++) {
                uint2 bb = *(const uint2*)&Vb[(j * 8 + g) * 68 + s * 8 + c2];
                mma8(O[j], a0, a1, a2, a3, bb.x, bb.y);
            }
        }
        buf ^= 1;
    }

    float* cb0 = ctx + ((size_t)(b * L_ + qg0)) * D_ + (bh & 15) * DKV;
    float* cb1 = cb0 + (size_t)8 * D_;
#pragma unroll
    for (int j = 0; j < 8; j++) {
        int col = j * 8 + c2;
        *(float2*)(cb0 + col) = make_float2(O[j].x, O[j].y);
        *(float2*)(cb1 + col) = make_float2(O[j].z, O[j].w);
    }
}

// ---------------------------------------------------------------------------
// LayerNorm over D_=1024
// ---------------------------------------------------------------------------
__device__ __forceinline__ float warp_sum(float v) {
#pragma unroll
    for (int o = 16; o; o >>= 1) v += __shfl_xor_sync(0xffffffffu, v, o);
    return v;
}

__global__ __launch_bounds__(256) void ln_kernel(
    const float* __restrict__ X, const float* __restrict__ gamma,
    const float* __restrict__ beta, float* __restrict__ O)
{
    const float* x = X + (size_t)blockIdx.x * D_;
    const int tid = threadIdx.x;
    __shared__ float rs[8], rq[8];

    float4 v = *(const float4*)(x + tid * 4);
    float s  = v.x + v.y + v.z + v.w;
    float q2 = v.x * v.x + v.y * v.y + v.z * v.z + v.w * v.w;
    s  = warp_sum(s);
    q2 = warp_sum(q2);
    if ((tid & 31) == 0) { rs[tid >> 5] = s; rq[tid >> 5] = q2; }
    __syncthreads();
    float S = 0.f, Q = 0.f;
#pragma unroll
    for (int w = 0; w < 8; w++) { S += rs[w]; Q += rq[w]; }
    float mu  = S * (1.0f / D_);
    float var = Q * (1.0f / D_) - mu * mu;
    float inv = rsqrtf(var + 1e-5f);

    float4 gmm = *(const float4*)(gamma + tid * 4);
    float4 bb  = *(const float4*)(beta + tid * 4);
    float4 o;
    o.x = (v.x - mu) * inv * gmm.x + bb.x;
    o.y = (v.y - mu) * inv * gmm.y + bb.y;
    o.z = (v.z - mu) * inv * gmm.z + bb.z;
    o.w = (v.w - mu) * inv * gmm.w + bb.w;
    *(float4*)(O + (size_t)blockIdx.x * D_ + tid * 4) = o;
}

// ---------------------------------------------------------------------------
// Launch
// ---------------------------------------------------------------------------
extern "C" void kernel_launch(void* const* d_in, const int* in_sizes, int n_in,
                              void* d_out, int out_size)
{
    const float*         q     = (const float*)d_in[0];
    const float*         k     = (const float*)d_in[1];
    const float*         v     = (const float*)d_in[2];
    const unsigned char* mask  = (const unsigned char*)d_in[4];
    const float*         Wq    = (const float*)d_in[5];
    const float*         bq    = (const float*)d_in[6];
    const float*         Wk    = (const float*)d_in[7];
    const float*         bk    = (const float*)d_in[8];
    const float*         Wv    = (const float*)d_in[9];
    const float*         bv    = (const float*)d_in[10];
    const float*         Wo    = (const float*)d_in[11];
    const float*         bo    = (const float*)d_in[12];
    const float*         gamma = (const float*)d_in[13];
    const float*         beta  = (const float*)d_in[14];
    float*               out   = (float*)d_out;

    float *qh, *kh, *vt, *ctx, *xb, *wt;
    unsigned long long* mpck;
    cudaGetSymbolAddress((void**)&qh,   g_qh);
    cudaGetSymbolAddress((void**)&kh,   g_kh);
    cudaGetSymbolAddress((void**)&vt,   g_vt);
    cudaGetSymbolAddress((void**)&ctx,  g_ctx);
    cudaGetSymbolAddress((void**)&xb,   g_x);
    cudaGetSymbolAddress((void**)&wt,   g_wt);
    cudaGetSymbolAddress((void**)&mpck, g_mp);

    const size_t n_out  = (size_t)B_ * L_ * D_;
    const size_t n_attn = (size_t)B_ * H_ * L_ * L_;
    int write_attn = ((size_t)out_size >= n_out + n_attn) ? 1 : 0;
    float* attn = write_attn ? out + n_out : nullptr;

    const int GEMM_SMEM = (2 * 128 * 40 + 2 * 128 * 36) * 4;   // 77824
    const int ATTN_SMEM = (4 * KT32 + 128 * 68) * 4;           // 104448
    cudaFuncSetAttribute(qkv_gemm,    cudaFuncAttributeMaxDynamicSharedMemorySize, GEMM_SMEM);
    cudaFuncSetAttribute(oproj_gemm,  cudaFuncAttributeMaxDynamicSharedMemorySize, GEMM_SMEM);
    cudaFuncSetAttribute(attn_kernel, cudaFuncAttributeMaxDynamicSharedMemorySize, ATTN_SMEM);

    dim3 gwt(D_ / 32, D_ / 32);
    wt_kernel<<<gwt, 256>>>(Wq, wt + 0 * D_ * D_);
    wt_kernel<<<gwt, 256>>>(Wk, wt + 1 * D_ * D_);
    wt_kernel<<<gwt, 256>>>(Wv, wt + 2 * D_ * D_);
    wt_kernel<<<gwt, 256>>>(Wo, wt + 3 * D_ * D_);
    pack_mask<<<(B_ * L_ * 32 + 255) / 256, 256>>>(mask, mpck);

    const int M = B_ * L_;                 // 8192
    dim3 gqkv(D_ / 128, M / 128, 3);

    qkv_gemm<<<gqkv, 256, GEMM_SMEM>>>(q, k, v,
        wt + 0 * D_ * D_, wt + 1 * D_ * D_, wt + 2 * D_ * D_,
        bq, bk, bv, qh, kh, vt);

    attn_kernel<<<dim3(L_ / 128, B_ * H_), 256, ATTN_SMEM>>>(qh, kh, vt, mpck, attn, ctx, write_attn);

    oproj_gemm<<<dim3(D_ / 128, M / 128), 256, GEMM_SMEM>>>(ctx, wt + 3 * D_ * D_, bo, q, xb);
    ln_kernel<<<M, 256>>>(xb, gamma, beta, out);
}

// round 10
// speedup vs baseline: 1.2039x; 1.2039x over previous
#include <cuda_runtime.h>
#include <math.h>
#include <cstddef>
#include <stdint.h>

#define B_   4
#define L_   2048
#define D_   1024
#define H_   16
#define DKV  64

// Q pre-scale: (1/sqrt(64)) * log2(e)  — softmax done in base-2 domain
#define QSCALE 0.18033688011112042f

// ---------------------------------------------------------------------------
// Scratch (allocation-free: __device__ globals)
// ---------------------------------------------------------------------------
static __device__ float g_qh [(size_t)B_ * L_ * D_];      // (b,l,h*dk) natural
static __device__ float g_kh [(size_t)B_ * L_ * D_];      // (b,l,h*dk) d 8-perm
static __device__ float g_vh [(size_t)B_ * L_ * D_];      // (b,l,h*dv) natural
static __device__ float g_ctx[(size_t)B_ * L_ * D_];
static __device__ float g_x  [(size_t)B_ * L_ * D_];
static __device__ float g_wt [4 * 1048576];               // Wt[n][k] tf32, k 8-perm
static __device__ unsigned long long g_mp[(size_t)B_ * L_ * 32];

// ---------------------------------------------------------------------------
// Helpers
// ---------------------------------------------------------------------------
__device__ __forceinline__ uint32_t f2tf(float f) {
    uint32_t u;
    asm("cvt.rna.tf32.f32 %0, %1;" : "=r"(u) : "f"(f));
    return u;
}
__device__ __forceinline__ float rndf(float x) { return __uint_as_float(f2tf(x)); }

__device__ __forceinline__ float ex2f(float x) {
    float r;
    asm("ex2.approx.ftz.f32 %0, %1;" : "=f"(r) : "f"(x));
    return r;
}

// pair-interleave perm within 8-group: position 2c holds elem c, 2c+1 holds c+4
__device__ __forceinline__ int perm8(int n) {
    return (n & ~7) | (((n & 3) << 1) | ((n & 7) >> 2));
}

__device__ __forceinline__ void mma8(float4& d,
    uint32_t a0, uint32_t a1, uint32_t a2, uint32_t a3,
    uint32_t b0, uint32_t b1)
{
    asm volatile(
        "mma.sync.aligned.m16n8k8.row.col.f32.tf32.tf32.f32 "
        "{%0,%1,%2,%3}, {%4,%5,%6,%7}, {%8,%9}, {%0,%1,%2,%3};"
        : "+f"(d.x), "+f"(d.y), "+f"(d.z), "+f"(d.w)
        : "r"(a0), "r"(a1), "r"(a2), "r"(a3), "r"(b0), "r"(b1));
}

__device__ __forceinline__ void cp16(uint32_t dst, const void* src) {
    asm volatile("cp.async.ca.shared.global [%0], [%1], 16;" :: "r"(dst), "l"(src));
}
__device__ __forceinline__ void cpcommit() { asm volatile("cp.async.commit_group;"); }
__device__ __forceinline__ void cpwait0()  { asm volatile("cp.async.wait_group 0;"); }
__device__ __forceinline__ void cpwait1()  { asm volatile("cp.async.wait_group 1;"); }

// ---------------------------------------------------------------------------
// Weight transpose + tf32 round: Wt[n][perm8(k)] = rnd(W[k][n])
// ---------------------------------------------------------------------------
__global__ __launch_bounds__(256) void wt_kernel(
    const float* __restrict__ W, float* __restrict__ Wt)
{
    __shared__ float t[32][33];
    const int kt = blockIdx.x * 32, nt = blockIdx.y * 32;
    const int tx = threadIdx.x & 31, ty = threadIdx.x >> 5;
#pragma unroll
    for (int r = ty; r < 32; r += 8)
        t[r][tx] = W[(size_t)(kt + r) * D_ + nt + tx];
    __syncthreads();
#pragma unroll
    for (int r = ty; r < 32; r += 8) {
        int kp = perm8(tx);
        Wt[(size_t)(nt + r) * D_ + kt + kp] = rndf(t[tx][r]);
    }
}

// ---------------------------------------------------------------------------
// Mask bit-packing
// ---------------------------------------------------------------------------
__global__ __launch_bounds__(256) void pack_mask(
    const unsigned char* __restrict__ mask, unsigned long long* __restrict__ mp)
{
    int idx = blockIdx.x * blockDim.x + threadIdx.x;
    if (idx >= B_ * L_ * 32) return;
    const unsigned* s = (const unsigned*)(mask + (size_t)idx * 64);
    unsigned long long bits = 0;
#pragma unroll
    for (int i = 0; i < 16; i++) {
        unsigned v = __ldg(s + i);
        unsigned t = ((v & 0x000000FFu) ? 1u : 0u)
                   | ((v & 0x0000FF00u) ? 2u : 0u)
                   | ((v & 0x00FF0000u) ? 4u : 0u)
                   | ((v & 0xFF000000u) ? 8u : 0u);
        bits |= (unsigned long long)t << (i * 4);
    }
    mp[idx] = bits;
}

// ---------------------------------------------------------------------------
// GEMM body: acc = A[M,K] @ Wt^T + bias. Wt is [n][k] (k 8-perm, tf32).
// modes: 0=qh(round,*QSCALE)  1=kh(round,col 8-perm scatter)
//        2=vh(round,natural)  3=out(+R raw)
// smem: As[2][128][40] + Wst[2][128][36]  (77824 B)
// ---------------------------------------------------------------------------
__device__ __forceinline__ void gemm_body(
    const float* __restrict__ A, const float* __restrict__ Wt,
    const float* __restrict__ bias, const float* __restrict__ R,
    float* __restrict__ C, int mode, char* smraw)
{
    float* As  = (float*)smraw;                  // 2*128*40
    float* Wst = (float*)smraw + 2 * 128 * 40;   // 2*128*36
    const int tid  = threadIdx.x;
    const int lane = tid & 31, wid = tid >> 5;
    const int wm = (wid & 3) * 32, wn = (wid >> 2) * 64;
    const int g = lane >> 2, c = lane & 3;
    const int bm = blockIdx.y * 128, bn = blockIdx.x * 128;
    const int K = D_, N = D_;

    uint32_t asBase = (uint32_t)__cvta_generic_to_shared(As);
    uint32_t wsBase = (uint32_t)__cvta_generic_to_shared(Wst);

    auto issue = [&](int buf, int kt) {
#pragma unroll
        for (int u = 0; u < 4; u++) {
            int i = tid + u * 256;
            int r = i >> 3, off = (i & 7) << 2;
            cp16(asBase + (uint32_t)(buf * 5120 + r * 40 + off) * 4,
                 A + (size_t)(bm + r) * K + kt + off);
        }
#pragma unroll
        for (int u = 0; u < 4; u++) {
            int i = tid + u * 256;
            int r = i >> 3, off = (i & 7) << 2;
            cp16(wsBase + (uint32_t)(buf * 4608 + r * 36 + off) * 4,
                 Wt + (size_t)(bn + r) * K + kt + off);
        }
        cpcommit();
    };

    float4 acc[2][8];
#pragma unroll
    for (int mi = 0; mi < 2; mi++)
#pragma unroll
        for (int j = 0; j < 8; j++) acc[mi][j] = make_float4(0.f, 0.f, 0.f, 0.f);

    issue(0, 0);
    int buf = 0;
    for (int kt = 0; kt < K; kt += 32) {
        if (kt + 32 < K) { issue(buf ^ 1, kt + 32); cpwait1(); }
        else             { cpwait0(); }
        __syncthreads();
        const float* Ab = As  + buf * 5120;
        const float* Wb = Wst + buf * 4608;
#pragma unroll
        for (int kk = 0; kk < 32; kk += 8) {
            uint32_t a[2][4];
#pragma unroll
            for (int mi = 0; mi < 2; mi++) {
                int r = wm + mi * 16;
                a[mi][0] = f2tf(Ab[(r + g    ) * 40 + kk + c]);
                a[mi][1] = f2tf(Ab[(r + g + 8) * 40 + kk + c]);
                a[mi][2] = f2tf(Ab[(r + g    ) * 40 + kk + c + 4]);
                a[mi][3] = f2tf(Ab[(r + g + 8) * 40 + kk + c + 4]);
            }
#pragma unroll
            for (int j = 0; j < 8; j++) {
                uint2 bb = *(const uint2*)&Wb[(wn + j * 8 + g) * 36 + kk + (c << 1)];
                mma8(acc[0][j], a[0][0], a[0][1], a[0][2], a[0][3], bb.x, bb.y);
                mma8(acc[1][j], a[1][0], a[1][1], a[1][2], a[1][3], bb.x, bb.y);
            }
        }
        __syncthreads();
        buf ^= 1;
    }

#pragma unroll
    for (int mi = 0; mi < 2; mi++) {
#pragma unroll
        for (int j = 0; j < 8; j++) {
            int r0  = bm + wm + mi * 16 + g;
            int col = bn + wn + j * 8 + (c << 1);
            float bx = bias[col], by = bias[col + 1];
            float2 v0 = { acc[mi][j].x + bx, acc[mi][j].y + by };
            float2 v1 = { acc[mi][j].z + bx, acc[mi][j].w + by };
            if (mode == 0) {
                v0.x = rndf(v0.x * QSCALE); v0.y = rndf(v0.y * QSCALE);
                v1.x = rndf(v1.x * QSCALE); v1.y = rndf(v1.y * QSCALE);
                *(float2*)(C + (size_t)r0 * N + col)       = v0;
                *(float2*)(C + (size_t)(r0 + 8) * N + col) = v1;
            } else if (mode == 1) {
                int c0 = perm8(col), c1 = perm8(col + 1);
                C[(size_t)r0 * N + c0]       = rndf(v0.x);
                C[(size_t)r0 * N + c1]       = rndf(v0.y);
                C[(size_t)(r0 + 8) * N + c0] = rndf(v1.x);
                C[(size_t)(r0 + 8) * N + c1] = rndf(v1.y);
            } else if (mode == 2) {
                v0.x = rndf(v0.x); v0.y = rndf(v0.y);
                v1.x = rndf(v1.x); v1.y = rndf(v1.y);
                *(float2*)(C + (size_t)r0 * N + col)       = v0;
                *(float2*)(C + (size_t)(r0 + 8) * N + col) = v1;
            } else {
                float2 r0v = *(const float2*)(R + (size_t)r0 * N + col);
                float2 r1v = *(const float2*)(R + (size_t)(r0 + 8) * N + col);
                v0.x += r0v.x; v0.y += r0v.y;
                v1.x += r1v.x; v1.y += r1v.y;
                *(float2*)(C + (size_t)r0 * N + col)       = v0;
                *(float2*)(C + (size_t)(r0 + 8) * N + col) = v1;
            }
        }
    }
}

__global__ __launch_bounds__(256, 2) void qkv_gemm(
    const float* q, const float* k, const float* v,
    const float* Wtq, const float* Wtk, const float* Wtv,
    const float* bq, const float* bk, const float* bv,
    float* qh, float* kh, float* vh)
{
    extern __shared__ char sm[];
    int z = blockIdx.z;
    const float* A  = z == 0 ? q   : (z == 1 ? k   : v);
    const float* Wt = z == 0 ? Wtq : (z == 1 ? Wtk : Wtv);
    const float* b  = z == 0 ? bq  : (z == 1 ? bk  : bv);
    float*       C  = z == 0 ? qh  : (z == 1 ? kh  : vh);
    gemm_body(A, Wt, b, nullptr, C, z, sm);
}

__global__ __launch_bounds__(256, 2) void oproj_gemm(
    const float* ctx, const float* Wto, const float* bo,
    const float* R, float* C)
{
    extern __shared__ char sm[];
    gemm_body(ctx, Wto, bo, R, C, 3, sm);
}

// ---------------------------------------------------------------------------
// Fused attention: 128q block, K tiles of 64, two passes, no-max base-2
// softmax. K/V cp.async double-buffered; pad-72 rows (conflict-free for all
// access patterns). smem (u32): Ks[2][64*72] Vs[2][64*72] Ps[128*72]
//  = (2*4608)*2 + 9216 = 27648 u32 = 110592 B.
// ---------------------------------------------------------------------------
#define KROW 72
#define KT32 (64 * KROW)     // 4608

__global__ __launch_bounds__(256, 2) void attn_kernel(
    const float* __restrict__ qh, const float* __restrict__ kh,
    const float* __restrict__ vh, const unsigned long long* __restrict__ mp,
    float* __restrict__ attn, float* __restrict__ ctx, int write_attn)
{
    extern __shared__ uint32_t smu[];
    uint32_t* Ks = smu;                   // 2 bufs
    uint32_t* Vs = smu + 2 * KT32;        // 2 bufs
    uint32_t* Ps = smu + 4 * KT32;        // 128*72

    const int tid  = threadIdx.x;
    const int lane = tid & 31, wid = tid >> 5;
    const int g = lane >> 2, c = lane & 3;
    const int c2 = c << 1;
    const int q0 = blockIdx.x * 128;
    const int bh = blockIdx.y, b = bh >> 4, h = bh & 15;
    const int qw = wid * 16;

    const uint32_t smemB = (uint32_t)__cvta_generic_to_shared(smu);

    // Q fragments in registers (qh pre-scaled ×QSCALE, tf32, natural layout)
    uint32_t aq[8][4];
    {
        const float* qb = qh + ((size_t)(b * L_ + q0 + qw)) * D_ + h * DKV;
#pragma unroll
        for (int s = 0; s < 8; s++) {
            aq[s][0] = __float_as_uint(__ldg(qb + (size_t)g       * D_ + s * 8 + c));
            aq[s][1] = __float_as_uint(__ldg(qb + (size_t)(g + 8) * D_ + s * 8 + c));
            aq[s][2] = __float_as_uint(__ldg(qb + (size_t)g       * D_ + s * 8 + c + 4));
            aq[s][3] = __float_as_uint(__ldg(qb + (size_t)(g + 8) * D_ + s * 8 + c + 4));
        }
    }

    auto issueK = [&](int bufi, int kt) {
        const float* kb = kh + ((size_t)(b * L_ + kt)) * D_ + h * DKV;
#pragma unroll
        for (int u = 0; u < 4; u++) {
            int i = tid + u * 256;
            int r = i >> 4, coff = (i & 15) << 2;
            cp16(smemB + (uint32_t)(bufi * KT32 + r * KROW + coff) * 4,
                 kb + (size_t)r * D_ + coff);
        }
    };
    auto issueV = [&](int bufi, int kt) {
        const float* vb = vh + ((size_t)(b * L_ + kt)) * D_ + h * DKV;
#pragma unroll
        for (int u = 0; u < 4; u++) {
            int i = tid + u * 256;
            int r = i >> 4, coff = (i & 15) << 2;
            cp16(smemB + (uint32_t)((2 + bufi) * KT32 + r * KROW + coff) * 4,
                 vb + (size_t)r * D_ + coff);
        }
    };

    const int qg0 = q0 + qw + g;
    const int qg1 = qg0 + 8;
    const unsigned long long* mp0 = mp + (size_t)(b * L_ + qg0) * 32;
    const unsigned long long* mp1 = mp + (size_t)(b * L_ + qg1) * 32;

    float l0 = 0.f, l1 = 0.f;

    // ---------------- PASS 1: row sums of exp2 (no max needed) ----------------
    issueK(0, 0); cpcommit();
    int buf = 0;
    for (int kt = 0; kt < L_; kt += 64) {
        cpwait0();
        __syncthreads();
        if (kt + 64 < L_) { issueK(buf ^ 1, kt + 64); cpcommit(); }

        const uint32_t* Kb = Ks + buf * KT32;
        float4 S[8];
#pragma unroll
        for (int j = 0; j < 8; j++) S[j] = make_float4(0.f, 0.f, 0.f, 0.f);
#pragma unroll
        for (int s = 0; s < 8; s++) {
#pragma unroll
            for (int j = 0; j < 8; j++) {
                uint2 bb = *(const uint2*)&Kb[(j * 8 + g) * KROW + s * 8 + c2];
                mma8(S[j], aq[s][0], aq[s][1], aq[s][2], aq[s][3], bb.x, bb.y);
            }
        }

        unsigned long long w0 = mp0[kt >> 6], w1 = mp1[kt >> 6];
        if (w0 | w1) {
#pragma unroll
            for (int j = 0; j < 8; j++) {
                int bi = j * 8 + c2;
                if ((w0 >> bi)       & 1) S[j].x = -INFINITY;
                if ((w0 >> (bi + 1)) & 1) S[j].y = -INFINITY;
                if ((w1 >> bi)       & 1) S[j].z = -INFINITY;
                if ((w1 >> (bi + 1)) & 1) S[j].w = -INFINITY;
            }
        }
#pragma unroll
        for (int j = 0; j < 8; j++) {
            l0 += ex2f(S[j].x) + ex2f(S[j].y);
            l1 += ex2f(S[j].z) + ex2f(S[j].w);
        }
        buf ^= 1;
    }
    l0 += __shfl_xor_sync(0xffffffffu, l0, 1);
    l0 += __shfl_xor_sync(0xffffffffu, l0, 2);
    l1 += __shfl_xor_sync(0xffffffffu, l1, 1);
    l1 += __shfl_xor_sync(0xffffffffu, l1, 2);
    const float inv0 = 1.0f / l0;
    const float inv1 = 1.0f / l1;

    // ---------------- PASS 2: attn write + O = P@V ----------------
    float4 O[8];
#pragma unroll
    for (int j = 0; j < 8; j++) O[j] = make_float4(0.f, 0.f, 0.f, 0.f);

    // Ks[0]/Vs[0]: Ks[0] last read 2 tiles before the final pass-1 barrier;
    // Vs untouched in pass 1. Safe to refill.
    issueK(0, 0); issueV(0, 0); cpcommit();
    buf = 0;
    for (int kt = 0; kt < L_; kt += 64) {
        cpwait0();
        __syncthreads();
        if (kt + 64 < L_) { issueK(buf ^ 1, kt + 64); issueV(buf ^ 1, kt + 64); cpcommit(); }

        const uint32_t* Kb = Ks + buf * KT32;
        const uint32_t* Vb = Vs + buf * KT32;
        float4 S[8];
#pragma unroll
        for (int j = 0; j < 8; j++) S[j] = make_float4(0.f, 0.f, 0.f, 0.f);
#pragma unroll
        for (int s = 0; s < 8; s++) {
#pragma unroll
            for (int j = 0; j < 8; j++) {
                uint2 bb = *(const uint2*)&Kb[(j * 8 + g) * KROW + s * 8 + c2];
                mma8(S[j], aq[s][0], aq[s][1], aq[s][2], aq[s][3], bb.x, bb.y);
            }
        }

        unsigned long long w0 = mp0[kt >> 6], w1 = mp1[kt >> 6];
        bool anymask = (w0 | w1) != 0ull;
#pragma unroll
        for (int j = 0; j < 8; j++) {
            float px = ex2f(S[j].x) * inv0;
            float py = ex2f(S[j].y) * inv0;
            float pz = ex2f(S[j].z) * inv1;
            float pw = ex2f(S[j].w) * inv1;
            if (anymask) {
                int bi = j * 8 + c2;
                if ((w0 >> bi)       & 1) px = 0.f;
                if ((w0 >> (bi + 1)) & 1) py = 0.f;
                if ((w1 >> bi)       & 1) pz = 0.f;
                if ((w1 >> (bi + 1)) & 1) pw = 0.f;
            }
            int kcol = kt + j * 8 + c2;
            if (write_attn) {
                *(float2*)(attn + ((size_t)bh * L_ + qg0) * L_ + kcol) = make_float2(px, py);
                *(float2*)(attn + ((size_t)bh * L_ + qg1) * L_ + kcol) = make_float2(pz, pw);
            }
            uint2 p01 = { f2tf(px), f2tf(py) };
            uint2 p23 = { f2tf(pz), f2tf(pw) };
            *(uint2*)&Ps[(qw + g    ) * KROW + j * 8 + c2] = p01;
            *(uint2*)&Ps[(qw + g + 8) * KROW + j * 8 + c2] = p23;
        }
        __syncwarp();   // Ps rows qw..qw+15 are warp-private

        // O += P @ V : P pair-interleaved in Ps, V natural [token][dv]
#pragma unroll
        for (int s = 0; s < 8; s++) {
            uint32_t a0 = Ps[(qw + g    ) * KROW + s * 8 + c];
            uint32_t a1 = Ps[(qw + g + 8) * KROW + s * 8 + c];
            uint32_t a2 = Ps[(qw + g    ) * KROW + s * 8 + c + 4];
            uint32_t a3 = Ps[(qw + g + 8) * KROW + s * 8 + c + 4];
#pragma unroll
            for (int j = 0; j < 8; j++) {
                uint32_t b0 = Vb[(s * 8 + c    ) * KROW + j * 8 + g];
                uint32_t b1 = Vb[(s * 8 + c + 4) * KROW + j * 8 + g];
                mma8(O[j], a0, a1, a2, a3, b0, b1);
            }
        }
        buf ^= 1;
    }

    float* cb0 = ctx + ((size_t)(b * L_ + qg0)) * D_ + h * DKV;
    float* cb1 = cb0 + (size_t)8 * D_;
#pragma unroll
    for (int j = 0; j < 8; j++) {
        int col = j * 8 + c2;
        *(float2*)(cb0 + col) = make_float2(O[j].x, O[j].y);
        *(float2*)(cb1 + col) = make_float2(O[j].z, O[j].w);
    }
}

// ---------------------------------------------------------------------------
// LayerNorm over D_=1024
// ---------------------------------------------------------------------------
__device__ __forceinline__ float warp_sum(float v) {
#pragma unroll
    for (int o = 16; o; o >>= 1) v += __shfl_xor_sync(0xffffffffu, v, o);
    return v;
}

__global__ __launch_bounds__(256) void ln_kernel(
    const float* __restrict__ X, const float* __restrict__ gamma,
    const float* __restrict__ beta, float* __restrict__ O)
{
    const float* x = X + (size_t)blockIdx.x * D_;
    const int tid = threadIdx.x;
    __shared__ float rs[8], rq[8];

    float4 v = *(const float4*)(x + tid * 4);
    float s  = v.x + v.y + v.z + v.w;
    float q2 = v.x * v.x + v.y * v.y + v.z * v.z + v.w * v.w;
    s  = warp_sum(s);
    q2 = warp_sum(q2);
    if ((tid & 31) == 0) { rs[tid >> 5] = s; rq[tid >> 5] = q2; }
    __syncthreads();
    float S = 0.f, Q = 0.f;
#pragma unroll
    for (int w = 0; w < 8; w++) { S += rs[w]; Q += rq[w]; }
    float mu  = S * (1.0f / D_);
    float var = Q * (1.0f / D_) - mu * mu;
    float inv = rsqrtf(var + 1e-5f);

    float4 gmm = *(const float4*)(gamma + tid * 4);
    float4 bb  = *(const float4*)(beta + tid * 4);
    float4 o;
    o.x = (v.x - mu) * inv * gmm.x + bb.x;
    o.y = (v.y - mu) * inv * gmm.y + bb.y;
    o.z = (v.z - mu) * inv * gmm.z + bb.z;
    o.w = (v.w - mu) * inv * gmm.w + bb.w;
    *(float4*)(O + (size_t)blockIdx.x * D_ + tid * 4) = o;
}

// ---------------------------------------------------------------------------
// Launch
// ---------------------------------------------------------------------------
extern "C" void kernel_launch(void* const* d_in, const int* in_sizes, int n_in,
                              void* d_out, int out_size)
{
    const float*         q     = (const float*)d_in[0];
    const float*         k     = (const float*)d_in[1];
    const float*         v     = (const float*)d_in[2];
    const unsigned char* mask  = (const unsigned char*)d_in[4];
    const float*         Wq    = (const float*)d_in[5];
    const float*         bq    = (const float*)d_in[6];
    const float*         Wk    = (const float*)d_in[7];
    const float*         bk    = (const float*)d_in[8];
    const float*         Wv    = (const float*)d_in[9];
    const float*         bv    = (const float*)d_in[10];
    const float*         Wo    = (const float*)d_in[11];
    const float*         bo    = (const float*)d_in[12];
    const float*         gamma = (const float*)d_in[13];
    const float*         beta  = (const float*)d_in[14];
    float*               out   = (float*)d_out;

    float *qh, *kh, *vh, *ctx, *xb, *wt;
    unsigned long long* mpck;
    cudaGetSymbolAddress((void**)&qh,   g_qh);
    cudaGetSymbolAddress((void**)&kh,   g_kh);
    cudaGetSymbolAddress((void**)&vh,   g_vh);
    cudaGetSymbolAddress((void**)&ctx,  g_ctx);
    cudaGetSymbolAddress((void**)&xb,   g_x);
    cudaGetSymbolAddress((void**)&wt,   g_wt);
    cudaGetSymbolAddress((void**)&mpck, g_mp);

    const size_t n_out  = (size_t)B_ * L_ * D_;
    const size_t n_attn = (size_t)B_ * H_ * L_ * L_;
    int write_attn = ((size_t)out_size >= n_out + n_attn) ? 1 : 0;
    float* attn = write_attn ? out + n_out : nullptr;

    const int GEMM_SMEM = (2 * 128 * 40 + 2 * 128 * 36) * 4;   // 77824
    const int ATTN_SMEM = (4 * KT32 + 128 * KROW) * 4;         // 110592
    cudaFuncSetAttribute(qkv_gemm,    cudaFuncAttributeMaxDynamicSharedMemorySize, GEMM_SMEM);
    cudaFuncSetAttribute(oproj_gemm,  cudaFuncAttributeMaxDynamicSharedMemorySize, GEMM_SMEM);
    cudaFuncSetAttribute(attn_kernel, cudaFuncAttributeMaxDynamicSharedMemorySize, ATTN_SMEM);

    dim3 gwt(D_ / 32, D_ / 32);
    wt_kernel<<<gwt, 256>>>(Wq, wt + 0 * D_ * D_);
    wt_kernel<<<gwt, 256>>>(Wk, wt + 1 * D_ * D_);
    wt_kernel<<<gwt, 256>>>(Wv, wt + 2 * D_ * D_);
    wt_kernel<<<gwt, 256>>>(Wo, wt + 3 * D_ * D_);
    pack_mask<<<(B_ * L_ * 32 + 255) / 256, 256>>>(mask, mpck);

    const int M = B_ * L_;                 // 8192
    dim3 gqkv(D_ / 128, M / 128, 3);

    qkv_gemm<<<gqkv, 256, GEMM_SMEM>>>(q, k, v,
        wt + 0 * D_ * D_, wt + 1 * D_ * D_, wt + 2 * D_ * D_,
        bq, bk, bv, qh, kh, vh);

    attn_kernel<<<dim3(L_ / 128, B_ * H_), 256, ATTN_SMEM>>>(qh, kh, vh, mpck, attn, ctx, write_attn);

    oproj_gemm<<<dim3(D_ / 128, M / 128), 256, GEMM_SMEM>>>(ctx, wt + 3 * D_ * D_, bo, q, xb);
    ln_kernel<<<M, 256>>>(xb, gamma, beta, out);
}

// round 14
// speedup vs baseline: 1.3919x; 1.1561x over previous
#include <cuda_runtime.h>
#include <math.h>
#include <cstddef>
#include <stdint.h>

#define B_   4
#define L_   2048
#define D_   1024
#define H_   16
#define DKV  64

// Q pre-scale: (1/sqrt(64)) * log2(e)  — softmax in base-2 domain
#define QSCALE 0.18033688011112042f

// ---------------------------------------------------------------------------
// Scratch (allocation-free: __device__ globals)
// ---------------------------------------------------------------------------
static __device__ float    g_qh [(size_t)B_ * L_ * D_];   // (b,l,h*dk) natural
static __device__ float    g_kh [(size_t)B_ * L_ * D_];   // (b,l,h*dk) d 8-perm
static __device__ float    g_vh [(size_t)B_ * L_ * D_];   // (b,l,h*dv) natural
static __device__ uint16_t g_vtb[(size_t)B_ * H_ * DKV * L_]; // bf16 (bh,dv,l)
static __device__ float    g_ctx[(size_t)B_ * L_ * D_];
static __device__ float    g_x  [(size_t)B_ * L_ * D_];
static __device__ float    g_wt [4 * 1048576];            // Wt[n][k] tf32, k 8-perm
static __device__ unsigned long long g_mp[(size_t)B_ * L_ * 32];

// ---------------------------------------------------------------------------
// Helpers
// ---------------------------------------------------------------------------
__device__ __forceinline__ uint32_t f2tf(float f) {
    uint32_t u;
    asm("cvt.rna.tf32.f32 %0, %1;" : "=r"(u) : "f"(f));
    return u;
}
__device__ __forceinline__ float rndf(float x) { return __uint_as_float(f2tf(x)); }

__device__ __forceinline__ uint16_t f2bf(float f) {
    uint16_t h;
    asm("cvt.rn.bf16.f32 %0, %1;" : "=h"(h) : "f"(f));
    return h;
}
// pack (lo, hi) -> bf16x2 (lo = element 0 = even k)
__device__ __forceinline__ uint32_t packbf(float lo, float hi) {
    uint32_t r;
    asm("cvt.rn.bf16x2.f32 %0, %1, %2;" : "=r"(r) : "f"(hi), "f"(lo));
    return r;
}

__device__ __forceinline__ float ex2f(float x) {
    float r;
    asm("ex2.approx.ftz.f32 %0, %1;" : "=f"(r) : "f"(x));
    return r;
}

// pair-interleave perm within 8-group (tf32 B-fragment pairs)
__device__ __forceinline__ int perm8(int n) {
    return (n & ~7) | (((n & 3) << 1) | ((n & 7) >> 2));
}

__device__ __forceinline__ void mma8(float4& d,
    uint32_t a0, uint32_t a1, uint32_t a2, uint32_t a3,
    uint32_t b0, uint32_t b1)
{
    asm volatile(
        "mma.sync.aligned.m16n8k8.row.col.f32.tf32.tf32.f32 "
        "{%0,%1,%2,%3}, {%4,%5,%6,%7}, {%8,%9}, {%0,%1,%2,%3};"
        : "+f"(d.x), "+f"(d.y), "+f"(d.z), "+f"(d.w)
        : "r"(a0), "r"(a1), "r"(a2), "r"(a3), "r"(b0), "r"(b1));
}

__device__ __forceinline__ void mma16(float4& d,
    uint32_t a0, uint32_t a1, uint32_t a2, uint32_t a3,
    uint32_t b0, uint32_t b1)
{
    asm volatile(
        "mma.sync.aligned.m16n8k16.row.col.f32.bf16.bf16.f32 "
        "{%0,%1,%2,%3}, {%4,%5,%6,%7}, {%8,%9}, {%0,%1,%2,%3};"
        : "+f"(d.x), "+f"(d.y), "+f"(d.z), "+f"(d.w)
        : "r"(a0), "r"(a1), "r"(a2), "r"(a3), "r"(b0), "r"(b1));
}

__device__ __forceinline__ void cp16(uint32_t dst, const void* src) {
    asm volatile("cp.async.ca.shared.global [%0], [%1], 16;" :: "r"(dst), "l"(src));
}
__device__ __forceinline__ void cpcommit() { asm volatile("cp.async.commit_group;"); }
__device__ __forceinline__ void cpwait0()  { asm volatile("cp.async.wait_group 0;"); }
__device__ __forceinline__ void cpwait1()  { asm volatile("cp.async.wait_group 1;"); }

// ---------------------------------------------------------------------------
// Weight transpose + tf32 round: Wt[n][perm8(k)] = rnd(W[k][n])
// ---------------------------------------------------------------------------
__global__ __launch_bounds__(256) void wt_kernel(
    const float* __restrict__ W, float* __restrict__ Wt)
{
    __shared__ float t[32][33];
    const int kt = blockIdx.x * 32, nt = blockIdx.y * 32;
    const int tx = threadIdx.x & 31, ty = threadIdx.x >> 5;
#pragma unroll
    for (int r = ty; r < 32; r += 8)
        t[r][tx] = W[(size_t)(kt + r) * D_ + nt + tx];
    __syncthreads();
#pragma unroll
    for (int r = ty; r < 32; r += 8) {
        int kp = perm8(tx);
        Wt[(size_t)(nt + r) * D_ + kt + kp] = rndf(t[tx][r]);
    }
}

// ---------------------------------------------------------------------------
// V transpose: vh (b,l,h*64+dv) f32  ->  vt (b*16+h, dv, l) bf16
// 32(l) x 32(dv) smem tiles; both sides coalesced.
// ---------------------------------------------------------------------------
__global__ __launch_bounds__(256) void vtrans_kernel(
    const float* __restrict__ vh, uint16_t* __restrict__ vt)
{
    __shared__ float t[32][33];
    const int l0  = blockIdx.x * 32;
    const int dv0 = blockIdx.y * 32;
    const int bh  = blockIdx.z, b = bh >> 4, h = bh & 15;
    const int tx = threadIdx.x & 31, ty = threadIdx.x >> 5;
#pragma unroll
    for (int rr = 0; rr < 4; rr++) {
        int row = ty + rr * 8;      // l index
        t[row][tx] = vh[((size_t)(b * L_ + l0 + row)) * D_ + h * DKV + dv0 + tx];
    }
    __syncthreads();
#pragma unroll
    for (int rr = 0; rr < 4; rr++) {
        int row = ty + rr * 8;      // dv index
        vt[((size_t)(bh * DKV + dv0 + row)) * L_ + l0 + tx] = f2bf(t[tx][row]);
    }
}

// ---------------------------------------------------------------------------
// Mask bit-packing
// ---------------------------------------------------------------------------
__global__ __launch_bounds__(256) void pack_mask(
    const unsigned char* __restrict__ mask, unsigned long long* __restrict__ mp)
{
    int idx = blockIdx.x * blockDim.x + threadIdx.x;
    if (idx >= B_ * L_ * 32) return;
    const unsigned* s = (const unsigned*)(mask + (size_t)idx * 64);
    unsigned long long bits = 0;
#pragma unroll
    for (int i = 0; i < 16; i++) {
        unsigned v = __ldg(s + i);
        unsigned t = ((v & 0x000000FFu) ? 1u : 0u)
                   | ((v & 0x0000FF00u) ? 2u : 0u)
                   | ((v & 0x00FF0000u) ? 4u : 0u)
                   | ((v & 0xFF000000u) ? 8u : 0u);
        bits |= (unsigned long long)t << (i * 4);
    }
    mp[idx] = bits;
}

// ---------------------------------------------------------------------------
// GEMM body (round-10, passing): acc = A[M,K] @ Wt^T + bias. Wt [n][k] 8-perm.
// modes: 0=qh(rnd,*QSCALE)  1=kh(rnd,col 8-perm)  2=vh(raw)  3=out(+R raw)
// smem: As[2][128][40] + Wst[2][128][36]  (77824 B)
// ---------------------------------------------------------------------------
__device__ __forceinline__ void gemm_body(
    const float* __restrict__ A, const float* __restrict__ Wt,
    const float* __restrict__ bias, const float* __restrict__ R,
    float* __restrict__ C, int mode, char* smraw)
{
    float* As  = (float*)smraw;                  // 2*128*40
    float* Wst = (float*)smraw + 2 * 128 * 40;   // 2*128*36
    const int tid  = threadIdx.x;
    const int lane = tid & 31, wid = tid >> 5;
    const int wm = (wid & 3) * 32, wn = (wid >> 2) * 64;
    const int g = lane >> 2, c = lane & 3;
    const int bm = blockIdx.y * 128, bn = blockIdx.x * 128;
    const int K = D_, N = D_;

    uint32_t asBase = (uint32_t)__cvta_generic_to_shared(As);
    uint32_t wsBase = (uint32_t)__cvta_generic_to_shared(Wst);

    auto issue = [&](int buf, int kt) {
#pragma unroll
        for (int u = 0; u < 4; u++) {
            int i = tid + u * 256;
            int r = i >> 3, off = (i & 7) << 2;
            cp16(asBase + (uint32_t)(buf * 5120 + r * 40 + off) * 4,
                 A + (size_t)(bm + r) * K + kt + off);
        }
#pragma unroll
        for (int u = 0; u < 4; u++) {
            int i = tid + u * 256;
            int r = i >> 3, off = (i & 7) << 2;
            cp16(wsBase + (uint32_t)(buf * 4608 + r * 36 + off) * 4,
                 Wt + (size_t)(bn + r) * K + kt + off);
        }
        cpcommit();
    };

    float4 acc[2][8];
#pragma unroll
    for (int mi = 0; mi < 2; mi++)
#pragma unroll
        for (int j = 0; j < 8; j++) acc[mi][j] = make_float4(0.f, 0.f, 0.f, 0.f);

    issue(0, 0);
    int buf = 0;
    for (int kt = 0; kt < K; kt += 32) {
        if (kt + 32 < K) { issue(buf ^ 1, kt + 32); cpwait1(); }
        else             { cpwait0(); }
        __syncthreads();
        const float* Ab = As  + buf * 5120;
        const float* Wb = Wst + buf * 4608;
#pragma unroll
        for (int kk = 0; kk < 32; kk += 8) {
            uint32_t a[2][4];
#pragma unroll
            for (int mi = 0; mi < 2; mi++) {
                int r = wm + mi * 16;
                a[mi][0] = f2tf(Ab[(r + g    ) * 40 + kk + c]);
                a[mi][1] = f2tf(Ab[(r + g + 8) * 40 + kk + c]);
                a[mi][2] = f2tf(Ab[(r + g    ) * 40 + kk + c + 4]);
                a[mi][3] = f2tf(Ab[(r + g + 8) * 40 + kk + c + 4]);
            }
#pragma unroll
            for (int j = 0; j < 8; j++) {
                uint2 bb = *(const uint2*)&Wb[(wn + j * 8 + g) * 36 + kk + (c << 1)];
                mma8(acc[0][j], a[0][0], a[0][1], a[0][2], a[0][3], bb.x, bb.y);
                mma8(acc[1][j], a[1][0], a[1][1], a[1][2], a[1][3], bb.x, bb.y);
            }
        }
        __syncthreads();
        buf ^= 1;
    }

#pragma unroll
    for (int mi = 0; mi < 2; mi++) {
#pragma unroll
        for (int j = 0; j < 8; j++) {
            int r0  = bm + wm + mi * 16 + g;
            int col = bn + wn + j * 8 + (c << 1);
            float bx = bias[col], by = bias[col + 1];
            float2 v0 = { acc[mi][j].x + bx, acc[mi][j].y + by };
            float2 v1 = { acc[mi][j].z + bx, acc[mi][j].w + by };
            if (mode == 0) {
                v0.x = rndf(v0.x * QSCALE); v0.y = rndf(v0.y * QSCALE);
                v1.x = rndf(v1.x * QSCALE); v1.y = rndf(v1.y * QSCALE);
                *(float2*)(C + (size_t)r0 * N + col)       = v0;
                *(float2*)(C + (size_t)(r0 + 8) * N + col) = v1;
            } else if (mode == 1) {
                int c0 = perm8(col), c1 = perm8(col + 1);
                C[(size_t)r0 * N + c0]       = rndf(v0.x);
                C[(size_t)r0 * N + c1]       = rndf(v0.y);
                C[(size_t)(r0 + 8) * N + c0] = rndf(v1.x);
                C[(size_t)(r0 + 8) * N + c1] = rndf(v1.y);
            } else if (mode == 2) {
                *(float2*)(C + (size_t)r0 * N + col)       = v0;
                *(float2*)(C + (size_t)(r0 + 8) * N + col) = v1;
            } else {
                float2 r0v = *(const float2*)(R + (size_t)r0 * N + col);
                float2 r1v = *(const float2*)(R + (size_t)(r0 + 8) * N + col);
                v0.x += r0v.x; v0.y += r0v.y;
                v1.x += r1v.x; v1.y += r1v.y;
                *(float2*)(C + (size_t)r0 * N + col)       = v0;
                *(float2*)(C + (size_t)(r0 + 8) * N + col) = v1;
            }
        }
    }
}

__global__ __launch_bounds__(256, 2) void qkv_gemm(
    const float* q, const float* k, const float* v,
    const float* Wtq, const float* Wtk, const float* Wtv,
    const float* bq, const float* bk, const float* bv,
    float* qh, float* kh, float* vh)
{
    extern __shared__ char sm[];
    int z = blockIdx.z;
    const float* A  = z == 0 ? q   : (z == 1 ? k   : v);
    const float* Wt = z == 0 ? Wtq : (z == 1 ? Wtk : Wtv);
    const float* b  = z == 0 ? bq  : (z == 1 ? bk  : bv);
    float*       C  = z == 0 ? qh  : (z == 1 ? kh  : vh);
    gemm_body(A, Wt, b, nullptr, C, z, sm);
}

__global__ __launch_bounds__(256, 2) void oproj_gemm(
    const float* ctx, const float* Wto, const float* bo,
    const float* R, float* C)
{
    extern __shared__ char sm[];
    gemm_body(ctx, Wto, bo, R, C, 3, sm);
}

// ---------------------------------------------------------------------------
// Fused attention: 128q block, K tiles of 64, two passes, no-max base-2
// softmax. K (tf32, pad-72) + V (bf16 transposed [dv][l], pad-36) cp.async
// double-buffered. PV via m16n8k16 bf16 with P packed directly from the
// QK^T accumulator fragments (no Ps smem).
// smem (u32): Ks[2][64*72] + Vs[2][64*36] = 13824 u32 = 55296 B
// ---------------------------------------------------------------------------
#define KROW 72
#define KT32 (64 * KROW)     // 4608
#define VROW 36
#define VT32 (64 * VROW)     // 2304

__global__ __launch_bounds__(256, 2) void attn_kernel(
    const float* __restrict__ qh, const float* __restrict__ kh,
    const uint16_t* __restrict__ vt, const unsigned long long* __restrict__ mp,
    float* __restrict__ attn, float* __restrict__ ctx, int write_attn)
{
    extern __shared__ uint32_t smu[];
    uint32_t* Ks = smu;                   // 2 bufs tf32 K
    uint32_t* Vs = smu + 2 * KT32;        // 2 bufs bf16 V (transposed)

    const int tid  = threadIdx.x;
    const int lane = tid & 31, wid = tid >> 5;
    const int g = lane >> 2, c = lane & 3;
    const int c2 = c << 1;
    const int q0 = blockIdx.x * 128;
    const int bh = blockIdx.y, b = bh >> 4, h = bh & 15;
    const int qw = wid * 16;

    uint32_t smemB;
    asm("{ .reg .u64 t; cvta.to.shared.u64 t, %1; cvt.u32.u64 %0, t; }"
        : "=r"(smemB) : "l"(smu));

    // Q fragments in registers (qh pre-scaled ×QSCALE, tf32, natural layout)
    uint32_t aq[8][4];
    {
        const float* qb = qh + ((size_t)(b * L_ + q0 + qw)) * D_ + h * DKV;
#pragma unroll
        for (int s = 0; s < 8; s++) {
            aq[s][0] = __float_as_uint(__ldg(qb + (size_t)g       * D_ + s * 8 + c));
            aq[s][1] = __float_as_uint(__ldg(qb + (size_t)(g + 8) * D_ + s * 8 + c));
            aq[s][2] = __float_as_uint(__ldg(qb + (size_t)g       * D_ + s * 8 + c + 4));
            aq[s][3] = __float_as_uint(__ldg(qb + (size_t)(g + 8) * D_ + s * 8 + c + 4));
        }
    }

    auto issueK = [&](int bufi, int kt) {
        const float* kb = kh + ((size_t)(b * L_ + kt)) * D_ + h * DKV;
#pragma unroll
        for (int u = 0; u < 4; u++) {
            int i = tid + u * 256;
            int r = i >> 4, coff = (i & 15) << 2;
            cp16(smemB + (uint32_t)(bufi * KT32 + r * KROW + coff) * 4,
                 kb + (size_t)r * D_ + coff);
        }
    };
    // V tile: 64 dv rows x 64 tokens bf16 (128 B per row) from vt[bh][dv][l]
    auto issueV = [&](int bufi, int kt) {
        const uint16_t* vb = vt + ((size_t)bh * DKV) * L_ + kt;
#pragma unroll
        for (int u = 0; u < 2; u++) {
            int i = tid + u * 256;
            int r = i >> 3, qq = i & 7;          // r = dv row, qq = 16B chunk
            cp16(smemB + (uint32_t)((2 * KT32 + bufi * VT32 + r * VROW) * 4)
                    + (uint32_t)(qq << 4),
                 vb + (size_t)r * L_ + qq * 8);
        }
    };

    const int qg0 = q0 + qw + g;
    const int qg1 = qg0 + 8;
    const unsigned long long* mp0 = mp + (size_t)(b * L_ + qg0) * 32;
    const unsigned long long* mp1 = mp + (size_t)(b * L_ + qg1) * 32;

    float l0 = 0.f, l1 = 0.f;

    // ---------------- PASS 1: row sums of exp2 (no max needed) ----------------
    issueK(0, 0); cpcommit();
    int buf = 0;
    for (int kt = 0; kt < L_; kt += 64) {
        cpwait0();
        __syncthreads();
        if (kt + 64 < L_) { issueK(buf ^ 1, kt + 64); cpcommit(); }

        const uint32_t* Kb = Ks + buf * KT32;
        float4 S[8];
#pragma unroll
        for (int j = 0; j < 8; j++) S[j] = make_float4(0.f, 0.f, 0.f, 0.f);
#pragma unroll
        for (int s = 0; s < 8; s++) {
#pragma unroll
            for (int j = 0; j < 8; j++) {
                uint2 bb = *(const uint2*)&Kb[(j * 8 + g) * KROW + s * 8 + c2];
                mma8(S[j], aq[s][0], aq[s][1], aq[s][2], aq[s][3], bb.x, bb.y);
            }
        }

        unsigned long long w0 = mp0[kt >> 6], w1 = mp1[kt >> 6];
        if (w0 | w1) {
#pragma unroll
            for (int j = 0; j < 8; j++) {
                int bi = j * 8 + c2;
                if ((w0 >> bi)       & 1) S[j].x = -INFINITY;
                if ((w0 >> (bi + 1)) & 1) S[j].y = -INFINITY;
                if ((w1 >> bi)       & 1) S[j].z = -INFINITY;
                if ((w1 >> (bi + 1)) & 1) S[j].w = -INFINITY;
            }
        }
#pragma unroll
        for (int j = 0; j < 8; j++) {
            l0 += ex2f(S[j].x) + ex2f(S[j].y);
            l1 += ex2f(S[j].z) + ex2f(S[j].w);
        }
        buf ^= 1;
    }
    l0 += __shfl_xor_sync(0xffffffffu, l0, 1);
    l0 += __shfl_xor_sync(0xffffffffu, l0, 2);
    l1 += __shfl_xor_sync(0xffffffffu, l1, 1);
    l1 += __shfl_xor_sync(0xffffffffu, l1, 2);
    const float inv0 = 1.0f / l0;
    const float inv1 = 1.0f / l1;

    // ---------------- PASS 2: attn write + O = P@V (bf16 PV) ----------------
    float4 O[8];
#pragma unroll
    for (int j = 0; j < 8; j++) O[j] = make_float4(0.f, 0.f, 0.f, 0.f);

    issueK(0, 0); issueV(0, 0); cpcommit();
    buf = 0;
    for (int kt = 0; kt < L_; kt += 64) {
        cpwait0();
        __syncthreads();
        if (kt + 64 < L_) { issueK(buf ^ 1, kt + 64); issueV(buf ^ 1, kt + 64); cpcommit(); }

        const uint32_t* Kb = Ks + buf * KT32;
        const uint32_t* Vb = Vs + buf * VT32;
        float4 S[8];
#pragma unroll
        for (int j = 0; j < 8; j++) S[j] = make_float4(0.f, 0.f, 0.f, 0.f);
#pragma unroll
        for (int s = 0; s < 8; s++) {
#pragma unroll
            for (int j = 0; j < 8; j++) {
                uint2 bb = *(const uint2*)&Kb[(j * 8 + g) * KROW + s * 8 + c2];
                mma8(S[j], aq[s][0], aq[s][1], aq[s][2], aq[s][3], bb.x, bb.y);
            }
        }

        unsigned long long w0 = mp0[kt >> 6], w1 = mp1[kt >> 6];
        bool anymask = (w0 | w1) != 0ull;
        uint32_t pa[8], pb[8];   // P bf16x2 fragments: pa = rows g, pb = rows g+8
#pragma unroll
        for (int j = 0; j < 8; j++) {
            float px = ex2f(S[j].x) * inv0;
            float py = ex2f(S[j].y) * inv0;
            float pz = ex2f(S[j].z) * inv1;
            float pw = ex2f(S[j].w) * inv1;
            if (anymask) {
                int bi = j * 8 + c2;
                if ((w0 >> bi)       & 1) px = 0.f;
                if ((w0 >> (bi + 1)) & 1) py = 0.f;
                if ((w1 >> bi)       & 1) pz = 0.f;
                if ((w1 >> (bi + 1)) & 1) pw = 0.f;
            }
            int kcol = kt + j * 8 + c2;
            if (write_attn) {
                *(float2*)(attn + ((size_t)bh * L_ + qg0) * L_ + kcol) = make_float2(px, py);
                *(float2*)(attn + ((size_t)bh * L_ + qg1) * L_ + kcol) = make_float2(pz, pw);
            }
            pa[j] = packbf(px, py);
            pb[j] = packbf(pz, pw);
        }

        // O += P @ V : m16n8k16 bf16; A-frags direct from pa/pb,
        // B-frags from transposed V smem [dv][token-pairs]
#pragma unroll
        for (int s = 0; s < 4; s++) {       // k16 group = tokens 16s..16s+15
            uint32_t a0 = pa[2 * s],     a1 = pb[2 * s];
            uint32_t a2 = pa[2 * s + 1], a3 = pb[2 * s + 1];
#pragma unroll
            for (int j = 0; j < 8; j++) {   // j = dv group (n)
                uint32_t b0 = Vb[(j * 8 + g) * VROW + s * 8 + c];
                uint32_t b1 = Vb[(j * 8 + g) * VROW + s * 8 + c + 4];
                mma16(O[j], a0, a1, a2, a3, b0, b1);
            }
        }
        buf ^= 1;
    }

    float* cb0 = ctx + ((size_t)(b * L_ + qg0)) * D_ + h * DKV;
    float* cb1 = cb0 + (size_t)8 * D_;
#pragma unroll
    for (int j = 0; j < 8; j++) {
        int col = j * 8 + c2;
        *(float2*)(cb0 + col) = make_float2(O[j].x, O[j].y);
        *(float2*)(cb1 + col) = make_float2(O[j].z, O[j].w);
    }
}

// ---------------------------------------------------------------------------
// LayerNorm over D_=1024
// ---------------------------------------------------------------------------
__device__ __forceinline__ float warp_sum(float v) {
#pragma unroll
    for (int o = 16; o; o >>= 1) v += __shfl_xor_sync(0xffffffffu, v, o);
    return v;
}

__global__ __launch_bounds__(256) void ln_kernel(
    const float* __restrict__ X, const float* __restrict__ gamma,
    const float* __restrict__ beta, float* __restrict__ O)
{
    const float* x = X + (size_t)blockIdx.x * D_;
    const int tid = threadIdx.x;
    __shared__ float rs[8], rq[8];

    float4 v = *(const float4*)(x + tid * 4);
    float s  = v.x + v.y + v.z + v.w;
    float q2 = v.x * v.x + v.y * v.y + v.z * v.z + v.w * v.w;
    s  = warp_sum(s);
    q2 = warp_sum(q2);
    if ((tid & 31) == 0) { rs[tid >> 5] = s; rq[tid >> 5] = q2; }
    __syncthreads();
    float S = 0.f, Q = 0.f;
#pragma unroll
    for (int w = 0; w < 8; w++) { S += rs[w]; Q += rq[w]; }
    float mu  = S * (1.0f / D_);
    float var = Q * (1.0f / D_) - mu * mu;
    float inv = rsqrtf(var + 1e-5f);

    float4 gmm = *(const float4*)(gamma + tid * 4);
    float4 bb  = *(const float4*)(beta + tid * 4);
    float4 o;
    o.x = (v.x - mu) * inv * gmm.x + bb.x;
    o.y = (v.y - mu) * inv * gmm.y + bb.y;
    o.z = (v.z - mu) * inv * gmm.z + bb.z;
    o.w = (v.w - mu) * inv * gmm.w + bb.w;
    *(float4*)(O + (size_t)blockIdx.x * D_ + tid * 4) = o;
}

// ---------------------------------------------------------------------------
// Launch
// ---------------------------------------------------------------------------
extern "C" void kernel_launch(void* const* d_in, const int* in_sizes, int n_in,
                              void* d_out, int out_size)
{
    const float*         q     = (const float*)d_in[0];
    const float*         k     = (const float*)d_in[1];
    const float*         v     = (const float*)d_in[2];
    const unsigned char* mask  = (const unsigned char*)d_in[4];
    const float*         Wq    = (const float*)d_in[5];
    const float*         bq    = (const float*)d_in[6];
    const float*         Wk    = (const float*)d_in[7];
    const float*         bk    = (const float*)d_in[8];
    const float*         Wv    = (const float*)d_in[9];
    const float*         bv    = (const float*)d_in[10];
    const float*         Wo    = (const float*)d_in[11];
    const float*         bo    = (const float*)d_in[12];
    const float*         gamma = (const float*)d_in[13];
    const float*         beta  = (const float*)d_in[14];
    float*               out   = (float*)d_out;

    float *qh, *kh, *vh, *ctx, *xb, *wt;
    uint16_t* vtb;
    unsigned long long* mpck;
    cudaGetSymbolAddress((void**)&qh,   g_qh);
    cudaGetSymbolAddress((void**)&kh,   g_kh);
    cudaGetSymbolAddress((void**)&vh,   g_vh);
    cudaGetSymbolAddress((void**)&vtb,  g_vtb);
    cudaGetSymbolAddress((void**)&ctx,  g_ctx);
    cudaGetSymbolAddress((void**)&xb,   g_x);
    cudaGetSymbolAddress((void**)&wt,   g_wt);
    cudaGetSymbolAddress((void**)&mpck, g_mp);

    const size_t n_out  = (size_t)B_ * L_ * D_;
    const size_t n_attn = (size_t)B_ * H_ * L_ * L_;
    int write_attn = ((size_t)out_size >= n_out + n_attn) ? 1 : 0;
    float* attn = write_attn ? out + n_out : nullptr;

    const int GEMM_SMEM = (2 * 128 * 40 + 2 * 128 * 36) * 4;   // 77824
    const int ATTN_SMEM = (2 * KT32 + 2 * VT32) * 4;           // 55296
    cudaFuncSetAttribute(qkv_gemm,    cudaFuncAttributeMaxDynamicSharedMemorySize, GEMM_SMEM);
    cudaFuncSetAttribute(oproj_gemm,  cudaFuncAttributeMaxDynamicSharedMemorySize, GEMM_SMEM);
    cudaFuncSetAttribute(attn_kernel, cudaFuncAttributeMaxDynamicSharedMemorySize, ATTN_SMEM);

    dim3 gwt(D_ / 32, D_ / 32);
    wt_kernel<<<gwt, 256>>>(Wq, wt + 0 * D_ * D_);
    wt_kernel<<<gwt, 256>>>(Wk, wt + 1 * D_ * D_);
    wt_kernel<<<gwt, 256>>>(Wv, wt + 2 * D_ * D_);
    wt_kernel<<<gwt, 256>>>(Wo, wt + 3 * D_ * D_);
    pack_mask<<<(B_ * L_ * 32 + 255) / 256, 256>>>(mask, mpck);

    const int M = B_ * L_;                 // 8192
    dim3 gqkv(D_ / 128, M / 128, 3);

    qkv_gemm<<<gqkv, 256, GEMM_SMEM>>>(q, k, v,
        wt + 0 * D_ * D_, wt + 1 * D_ * D_, wt + 2 * D_ * D_,
        bq, bk, bv, qh, kh, vh);

    vtrans_kernel<<<dim3(L_ / 32, DKV / 32, B_ * H_), 256>>>(vh, vtb);

    attn_kernel<<<dim3(L_ / 128, B_ * H_), 256, ATTN_SMEM>>>(qh, kh, vtb, mpck, attn, ctx, write_attn);

    oproj_gemm<<<dim3(D_ / 128, M / 128), 256, GEMM_SMEM>>>(ctx, wt + 3 * D_ * D_, bo, q, xb);
    ln_kernel<<<M, 256>>>(xb, gamma, beta, out);
}